// round 2
// baseline (speedup 1.0000x reference)
#include <cuda_runtime.h>

#define D      128
#define TWO_D  256
#define H      128
#define H2     64
#define WARPS_PER_BLOCK 8
#define EPQ    4   // edges per warp ("quad")

__global__ void __launch_bounds__(256) lp_decoder(
    const float* __restrict__ z,
    const int* __restrict__ ei,      // int32 edge_index: [2, E] row-major
    const float* __restrict__ W1,
    const float* __restrict__ b1,
    const float* __restrict__ W2,
    const float* __restrict__ b2,
    const float* __restrict__ W3,
    const float* __restrict__ b3,
    float* __restrict__ out,
    int E, int n_nodes)
{
    __shared__ __align__(16) float xs[WARPS_PER_BLOCK][EPQ * TWO_D];  // 32 KB
    const int warp = threadIdx.x >> 5;
    const int lane = threadIdx.x & 31;
    const long long q  = (long long)blockIdx.x * WARPS_PER_BLOCK + warp;
    const long long e0 = q * EPQ;
    if (e0 >= (long long)E) return;

    float* xw = xs[warp];

    // ---- Stage gathered edge features into smem: x = [z_src | z_dst], 256 floats/edge ----
    #pragma unroll
    for (int e = 0; e < EPQ; e++) {
        long long eid = e0 + e;
        if (eid >= (long long)E) eid = (long long)E - 1;   // clamp (reads stay valid)
        int src = __ldg(ei + eid);
        int dst = __ldg(ei + (long long)E + eid);
        src = min(max(src, 0), n_nodes - 1);
        dst = min(max(dst, 0), n_nodes - 1);
        float4 vi = __ldg((const float4*)(z + (size_t)src * D) + lane);
        float4 vj = __ldg((const float4*)(z + (size_t)dst * D) + lane);
        ((float4*)(xw + e * TWO_D))[lane]     = vi;
        ((float4*)(xw + e * TWO_D + D))[lane] = vj;
    }
    __syncwarp();

    // ---- Layer 1: h1[j] = relu(b1[j] + sum_k x[k] * W1[k][j]); lane owns j = 4*lane..4*lane+3 ----
    const float4 b1v = __ldg((const float4*)b1 + lane);
    float acc[EPQ][4];
    #pragma unroll
    for (int e = 0; e < EPQ; e++) {
        acc[e][0] = b1v.x; acc[e][1] = b1v.y; acc[e][2] = b1v.z; acc[e][3] = b1v.w;
    }

    #pragma unroll 4
    for (int k = 0; k < TWO_D; k += 4) {
        const float4 w0 = __ldg((const float4*)(W1 + (size_t)(k + 0) * H) + lane);
        const float4 w1 = __ldg((const float4*)(W1 + (size_t)(k + 1) * H) + lane);
        const float4 w2 = __ldg((const float4*)(W1 + (size_t)(k + 2) * H) + lane);
        const float4 w3 = __ldg((const float4*)(W1 + (size_t)(k + 3) * H) + lane);
        #pragma unroll
        for (int e = 0; e < EPQ; e++) {
            const float4 xv = *(const float4*)(xw + e * TWO_D + k);  // broadcast LDS.128
            acc[e][0] = fmaf(xv.x, w0.x, acc[e][0]);
            acc[e][1] = fmaf(xv.x, w0.y, acc[e][1]);
            acc[e][2] = fmaf(xv.x, w0.z, acc[e][2]);
            acc[e][3] = fmaf(xv.x, w0.w, acc[e][3]);

            acc[e][0] = fmaf(xv.y, w1.x, acc[e][0]);
            acc[e][1] = fmaf(xv.y, w1.y, acc[e][1]);
            acc[e][2] = fmaf(xv.y, w1.z, acc[e][2]);
            acc[e][3] = fmaf(xv.y, w1.w, acc[e][3]);

            acc[e][0] = fmaf(xv.z, w2.x, acc[e][0]);
            acc[e][1] = fmaf(xv.z, w2.y, acc[e][1]);
            acc[e][2] = fmaf(xv.z, w2.z, acc[e][2]);
            acc[e][3] = fmaf(xv.z, w2.w, acc[e][3]);

            acc[e][0] = fmaf(xv.w, w3.x, acc[e][0]);
            acc[e][1] = fmaf(xv.w, w3.y, acc[e][1]);
            acc[e][2] = fmaf(xv.w, w3.z, acc[e][2]);
            acc[e][3] = fmaf(xv.w, w3.w, acc[e][3]);
        }
    }
    __syncwarp();   // all lanes done reading x before overwriting with h1

    // relu + store h1 into the (now consumed) x region: h1[e] at xw + e*TWO_D, j-contiguous
    #pragma unroll
    for (int e = 0; e < EPQ; e++) {
        float4 h;
        h.x = fmaxf(acc[e][0], 0.0f);
        h.y = fmaxf(acc[e][1], 0.0f);
        h.z = fmaxf(acc[e][2], 0.0f);
        h.w = fmaxf(acc[e][3], 0.0f);
        ((float4*)(xw + e * TWO_D))[lane] = h;
    }
    __syncwarp();

    // ---- Layer 2: h2[m] = relu(b2[m] + sum_j h1[j] * W2[j][m]); lane owns m = lane, lane+32 ----
    float acc2[EPQ][2];
    {
        const float b2a = __ldg(b2 + lane);
        const float b2b = __ldg(b2 + lane + 32);
        #pragma unroll
        for (int e = 0; e < EPQ; e++) { acc2[e][0] = b2a; acc2[e][1] = b2b; }
    }

    #pragma unroll 4
    for (int j = 0; j < H; j += 4) {
        float4 hq[EPQ];
        #pragma unroll
        for (int e = 0; e < EPQ; e++)
            hq[e] = *(const float4*)(xw + e * TWO_D + j);   // broadcast LDS.128
        #pragma unroll
        for (int t = 0; t < 4; t++) {
            const float wA = __ldg(W2 + (size_t)(j + t) * H2 + lane);
            const float wB = __ldg(W2 + (size_t)(j + t) * H2 + lane + 32);
            #pragma unroll
            for (int e = 0; e < EPQ; e++) {
                const float hv = (t == 0) ? hq[e].x : (t == 1) ? hq[e].y : (t == 2) ? hq[e].z : hq[e].w;
                acc2[e][0] = fmaf(hv, wA, acc2[e][0]);
                acc2[e][1] = fmaf(hv, wB, acc2[e][1]);
            }
        }
    }

    // ---- Layer 3: score = b3 + sum_m relu(h2[m]) * W3[m]; warp reduction per edge ----
    const float w3A = __ldg(W3 + lane);
    const float w3B = __ldg(W3 + lane + 32);
    const float b3v = __ldg(b3);
    #pragma unroll
    for (int e = 0; e < EPQ; e++) {
        float s = fmaxf(acc2[e][0], 0.0f) * w3A + fmaxf(acc2[e][1], 0.0f) * w3B;
        #pragma unroll
        for (int off = 16; off; off >>= 1)
            s += __shfl_xor_sync(0xffffffffu, s, off);
        if (lane == 0 && (e0 + e) < (long long)E)
            out[e0 + e] = s + b3v;
    }
}

extern "C" void kernel_launch(void* const* d_in, const int* in_sizes, int n_in,
                              void* d_out, int out_size)
{
    const float* z  = (const float*)d_in[0];
    const int*   ei = (const int*)d_in[1];     // int32 (harness dtype set: f32/i32/bf16)
    const float* W1 = (const float*)d_in[2];
    const float* b1 = (const float*)d_in[3];
    const float* W2 = (const float*)d_in[4];
    const float* b2 = (const float*)d_in[5];
    const float* W3 = (const float*)d_in[6];
    const float* b3 = (const float*)d_in[7];
    float* out = (float*)d_out;

    const int E       = in_sizes[1] / 2;       // edge_index has 2*E elements
    const int n_nodes = in_sizes[0] / D;
    const int quads   = (E + EPQ - 1) / EPQ;
    const int blocks  = (quads + WARPS_PER_BLOCK - 1) / WARPS_PER_BLOCK;
    lp_decoder<<<blocks, 256>>>(z, ei, W1, b1, W2, b2, W3, b3, out, E, n_nodes);
}

// round 3
// speedup vs baseline: 1.2004x; 1.2004x over previous
#include <cuda_runtime.h>

#define D      128
#define TWO_D  256
#define H      128
#define H2     64
#define WARPS_PER_BLOCK 4
#define EPQ    8   // edges per warp

__global__ void __launch_bounds__(128) lp_decoder(
    const float* __restrict__ z,
    const int* __restrict__ ei,      // int32 edge_index: [2, E]
    const float* __restrict__ W1,
    const float* __restrict__ b1,
    const float* __restrict__ W2,
    const float* __restrict__ b2,
    const float* __restrict__ W3,
    const float* __restrict__ b3,
    float* __restrict__ out,
    int E, int n_nodes)
{
    __shared__ __align__(16) float xs[WARPS_PER_BLOCK][EPQ * TWO_D];  // 32 KB
    const int warp = threadIdx.x >> 5;
    const int lane = threadIdx.x & 31;
    const int q  = blockIdx.x * WARPS_PER_BLOCK + warp;
    const long long e0 = (long long)q * EPQ;
    if (e0 >= (long long)E) return;

    float* xw = xs[warp];

    // ---- Stage gathered edge features: x = [z_src | z_dst], 256 floats/edge ----
    #pragma unroll
    for (int e = 0; e < EPQ; e++) {
        long long eid = e0 + e;
        if (eid >= (long long)E) eid = (long long)E - 1;
        int src = __ldg(ei + eid);
        int dst = __ldg(ei + (long long)E + eid);
        src = min(max(src, 0), n_nodes - 1);
        dst = min(max(dst, 0), n_nodes - 1);
        float4 vi = __ldg((const float4*)(z + (size_t)src * D) + lane);
        float4 vj = __ldg((const float4*)(z + (size_t)dst * D) + lane);
        ((float4*)(xw + e * TWO_D))[lane]     = vi;
        ((float4*)(xw + e * TWO_D + D))[lane] = vj;
    }
    __syncwarp();

    // ---- Layer 1: lane owns output cols j = 4*lane..4*lane+3; 8 edges in flight ----
    const float4 b1v = __ldg((const float4*)b1 + lane);
    float acc[EPQ][4];
    #pragma unroll
    for (int e = 0; e < EPQ; e++) {
        acc[e][0] = b1v.x; acc[e][1] = b1v.y; acc[e][2] = b1v.z; acc[e][3] = b1v.w;
    }

    #pragma unroll 2
    for (int k = 0; k < TWO_D; k += 4) {
        const float4 w0 = __ldg((const float4*)(W1 + (size_t)(k + 0) * H) + lane);
        const float4 w1 = __ldg((const float4*)(W1 + (size_t)(k + 1) * H) + lane);
        const float4 w2 = __ldg((const float4*)(W1 + (size_t)(k + 2) * H) + lane);
        const float4 w3 = __ldg((const float4*)(W1 + (size_t)(k + 3) * H) + lane);
        #pragma unroll
        for (int e = 0; e < EPQ; e++) {
            const float4 xv = *(const float4*)(xw + e * TWO_D + k);  // broadcast LDS.128
            acc[e][0] = fmaf(xv.x, w0.x, acc[e][0]);
            acc[e][1] = fmaf(xv.x, w0.y, acc[e][1]);
            acc[e][2] = fmaf(xv.x, w0.z, acc[e][2]);
            acc[e][3] = fmaf(xv.x, w0.w, acc[e][3]);

            acc[e][0] = fmaf(xv.y, w1.x, acc[e][0]);
            acc[e][1] = fmaf(xv.y, w1.y, acc[e][1]);
            acc[e][2] = fmaf(xv.y, w1.z, acc[e][2]);
            acc[e][3] = fmaf(xv.y, w1.w, acc[e][3]);

            acc[e][0] = fmaf(xv.z, w2.x, acc[e][0]);
            acc[e][1] = fmaf(xv.z, w2.y, acc[e][1]);
            acc[e][2] = fmaf(xv.z, w2.z, acc[e][2]);
            acc[e][3] = fmaf(xv.z, w2.w, acc[e][3]);

            acc[e][0] = fmaf(xv.w, w3.x, acc[e][0]);
            acc[e][1] = fmaf(xv.w, w3.y, acc[e][1]);
            acc[e][2] = fmaf(xv.w, w3.z, acc[e][2]);
            acc[e][3] = fmaf(xv.w, w3.w, acc[e][3]);
        }
    }
    __syncwarp();   // all lanes done reading x before overwrite

    // relu + store h1 over consumed x region: h1[e] at xw + e*TWO_D (j-contiguous)
    #pragma unroll
    for (int e = 0; e < EPQ; e++) {
        float4 h;
        h.x = fmaxf(acc[e][0], 0.0f);
        h.y = fmaxf(acc[e][1], 0.0f);
        h.z = fmaxf(acc[e][2], 0.0f);
        h.w = fmaxf(acc[e][3], 0.0f);
        ((float4*)(xw + e * TWO_D))[lane] = h;
    }
    __syncwarp();

    // ---- Layer 2: lane owns m = lane and m = lane+32 ----
    float acc2[EPQ][2];
    {
        const float b2a = __ldg(b2 + lane);
        const float b2b = __ldg(b2 + lane + 32);
        #pragma unroll
        for (int e = 0; e < EPQ; e++) { acc2[e][0] = b2a; acc2[e][1] = b2b; }
    }

    #pragma unroll 2
    for (int j = 0; j < H; j += 4) {
        float wA[4], wB[4];
        #pragma unroll
        for (int t = 0; t < 4; t++) {
            wA[t] = __ldg(W2 + (size_t)(j + t) * H2 + lane);
            wB[t] = __ldg(W2 + (size_t)(j + t) * H2 + lane + 32);
        }
        #pragma unroll
        for (int e = 0; e < EPQ; e++) {
            const float4 hv = *(const float4*)(xw + e * TWO_D + j);  // broadcast LDS.128
            acc2[e][0] = fmaf(hv.x, wA[0], acc2[e][0]);
            acc2[e][1] = fmaf(hv.x, wB[0], acc2[e][1]);
            acc2[e][0] = fmaf(hv.y, wA[1], acc2[e][0]);
            acc2[e][1] = fmaf(hv.y, wB[1], acc2[e][1]);
            acc2[e][0] = fmaf(hv.z, wA[2], acc2[e][0]);
            acc2[e][1] = fmaf(hv.z, wB[2], acc2[e][1]);
            acc2[e][0] = fmaf(hv.w, wA[3], acc2[e][0]);
            acc2[e][1] = fmaf(hv.w, wB[3], acc2[e][1]);
        }
    }

    // ---- Layer 3: score = b3 + sum_m relu(h2[m]) * W3[m]; warp butterfly per edge ----
    const float w3A = __ldg(W3 + lane);
    const float w3B = __ldg(W3 + lane + 32);
    const float b3v = __ldg(b3);
    #pragma unroll
    for (int e = 0; e < EPQ; e++) {
        float s = fmaxf(acc2[e][0], 0.0f) * w3A + fmaxf(acc2[e][1], 0.0f) * w3B;
        #pragma unroll
        for (int off = 16; off; off >>= 1)
            s += __shfl_xor_sync(0xffffffffu, s, off);
        if (lane == 0 && (e0 + e) < (long long)E)
            out[e0 + e] = s + b3v;
    }
}

extern "C" void kernel_launch(void* const* d_in, const int* in_sizes, int n_in,
                              void* d_out, int out_size)
{
    const float* z  = (const float*)d_in[0];
    const int*   ei = (const int*)d_in[1];
    const float* W1 = (const float*)d_in[2];
    const float* b1 = (const float*)d_in[3];
    const float* W2 = (const float*)d_in[4];
    const float* b2 = (const float*)d_in[5];
    const float* W3 = (const float*)d_in[6];
    const float* b3 = (const float*)d_in[7];
    float* out = (float*)d_out;

    const int E       = in_sizes[1] / 2;
    const int n_nodes = in_sizes[0] / D;
    const int quads   = (E + EPQ - 1) / EPQ;
    const int blocks  = (quads + WARPS_PER_BLOCK - 1) / WARPS_PER_BLOCK;
    lp_decoder<<<blocks, WARPS_PER_BLOCK * 32>>>(z, ei, W1, b1, W2, b2, W3, b3, out, E, n_nodes);
}

// round 4
// speedup vs baseline: 1.7198x; 1.4327x over previous
#include <cuda_runtime.h>
#include <cstdint>

#define TWO_D 256
#define H     128
#define H2    64
#define TILE_E 64

// dynamic smem layout (float/uint32 indices)
#define OFF_W1  0                         // 256*128 tf32
#define OFF_W2  (256*128)                 // 128*64 tf32
#define OFF_X   (OFF_W2 + 128*64)         // 64*256 tf32 (x, later h1)
#define OFF_IDX (OFF_X + 64*256)          // 128 int
#define OFF_PART (OFF_IDX + 128)          // 128 float
#define SMEM_FLOATS (OFF_PART + 128)      // 57600 * 4B = 230400 B

__device__ __forceinline__ uint32_t f2tf(float f) {
    uint32_t r;
    asm("cvt.rna.tf32.f32 %0, %1;" : "=r"(r) : "f"(f));
    return r;
}

__device__ __forceinline__ void mma_tf32(float c[4],
    uint32_t a0, uint32_t a1, uint32_t a2, uint32_t a3,
    uint32_t b0, uint32_t b1)
{
    asm volatile("mma.sync.aligned.m16n8k8.row.col.f32.tf32.tf32.f32 "
        "{%0,%1,%2,%3}, {%4,%5,%6,%7}, {%8,%9}, {%0,%1,%2,%3};"
        : "+f"(c[0]), "+f"(c[1]), "+f"(c[2]), "+f"(c[3])
        : "r"(a0), "r"(a1), "r"(a2), "r"(a3), "r"(b0), "r"(b1));
}

extern __shared__ float smem[];

__global__ void __launch_bounds__(128, 1) lp_tc(
    const float* __restrict__ z,
    const int*   __restrict__ ei,
    const float* __restrict__ W1,
    const float* __restrict__ b1,
    const float* __restrict__ W2,
    const float* __restrict__ b2,
    const float* __restrict__ W3,
    const float* __restrict__ b3,
    float* __restrict__ out,
    int E, int n_nodes, int ntiles)
{
    const int tid  = threadIdx.x;
    const int lane = tid & 31;
    const int wid  = tid >> 5;
    const int tg   = lane & 3;       // thread-in-group
    const int g    = lane >> 2;      // group id
    uint32_t* s32 = reinterpret_cast<uint32_t*>(smem);
    int*   sidx = reinterpret_cast<int*>(smem + OFF_IDX);
    float* part = smem + OFF_PART;

    // ---- one-time: W1 -> smem (tf32, swizzled n ^ ((k&3)<<3)) ----
    for (int i = tid; i < (TWO_D * H) / 4; i += 128) {
        int k  = i >> 5;             // 32 float4 per 128-wide row
        int nc = (i & 31) << 2;
        float4 v = __ldg((const float4*)(W1 + (size_t)k * H + nc));
        uint4 t; t.x = f2tf(v.x); t.y = f2tf(v.y); t.z = f2tf(v.z); t.w = f2tf(v.w);
        *reinterpret_cast<uint4*>(&s32[OFF_W1 + k * H + (nc ^ ((k & 3) << 3))]) = t;
    }
    // ---- one-time: W2 -> smem ----
    for (int i = tid; i < (H * H2) / 4; i += 128) {
        int k  = i >> 4;             // 16 float4 per 64-wide row
        int nc = (i & 15) << 2;
        float4 v = __ldg((const float4*)(W2 + (size_t)k * H2 + nc));
        uint4 t; t.x = f2tf(v.x); t.y = f2tf(v.y); t.z = f2tf(v.z); t.w = f2tf(v.w);
        *reinterpret_cast<uint4*>(&s32[OFF_W2 + k * H2 + (nc ^ ((k & 3) << 3))]) = t;
    }

    // warp tile assignment: group = edges [group*32, +32), nhalf = output col half
    const int group = wid >> 1;
    const int nhalf = wid & 1;
    const int nb1 = nhalf * 64;      // layer-1 col base (N=128 split in 2)
    const int nb2 = nhalf * 32;      // layer-2 col base (N=64 split in 2)

    // cached bias / W3 fragments (cols owned by this thread)
    float b1f[8][2], b2f[4][2], w3f[4][2];
    #pragma unroll
    for (int nt = 0; nt < 8; nt++) {
        b1f[nt][0] = __ldg(b1 + nb1 + nt * 8 + 2 * tg);
        b1f[nt][1] = __ldg(b1 + nb1 + nt * 8 + 2 * tg + 1);
    }
    #pragma unroll
    for (int nt = 0; nt < 4; nt++) {
        b2f[nt][0] = __ldg(b2 + nb2 + nt * 8 + 2 * tg);
        b2f[nt][1] = __ldg(b2 + nb2 + nt * 8 + 2 * tg + 1);
        w3f[nt][0] = __ldg(W3 + nb2 + nt * 8 + 2 * tg);
        w3f[nt][1] = __ldg(W3 + nb2 + nt * 8 + 2 * tg + 1);
    }
    const float b3v = __ldg(b3);
    __syncthreads();

    for (int tile = blockIdx.x; tile < ntiles; tile += gridDim.x) {
        const long long e0 = (long long)tile * TILE_E;

        // ---- stage edge indices ----
        {
            long long eid = e0 + (tid & 63);
            if (eid >= (long long)E) eid = (long long)E - 1;
            int v = (tid < 64) ? __ldg(ei + eid) : __ldg(ei + (long long)E + eid);
            sidx[tid] = min(max(v, 0), n_nodes - 1);
        }
        __syncthreads();

        // ---- gather x = [z_src | z_dst] -> smem tf32, swizzle k ^ ((e&7)<<2) ----
        for (int i = tid; i < TILE_E * 64; i += 128) {   // 64 float4 per edge
            int e = i >> 6;
            int c = i & 63;
            int node = sidx[(c < 32) ? e : (64 + e)];
            float4 v = __ldg((const float4*)(z + (size_t)node * 128) + (c & 31));
            int kbase = ((c & 31) << 2) + ((c >> 5) << 7);      // 0..252
            uint4 t; t.x = f2tf(v.x); t.y = f2tf(v.y); t.z = f2tf(v.z); t.w = f2tf(v.w);
            *reinterpret_cast<uint4*>(&s32[OFF_X + e * 256 + (kbase ^ ((e & 7) << 2))]) = t;
        }
        __syncthreads();

        // ---- layer 1: C[32 edges x 64 cols] = X @ W1, K=256 ----
        float acc[2][8][4];
        #pragma unroll
        for (int mt = 0; mt < 2; mt++)
            #pragma unroll
            for (int nt = 0; nt < 8; nt++)
                #pragma unroll
                for (int q = 0; q < 4; q++) acc[mt][nt][q] = 0.f;

        const uint32_t* xg = &s32[OFF_X + (group * 32) * 256];
        const int asw = g << 2;      // (e&7)<<2 with e&7 == g for all fragment rows
        const int bsw = tg << 3;
        #pragma unroll 4
        for (int kk = 0; kk < 32; kk++) {
            const int k0 = kk * 8;
            uint32_t a[2][4];
            #pragma unroll
            for (int mt = 0; mt < 2; mt++) {
                const int r1 = (mt * 16 + g) * 256;
                const int r2 = (mt * 16 + g + 8) * 256;
                a[mt][0] = xg[r1 + ((k0 + tg) ^ asw)];
                a[mt][1] = xg[r2 + ((k0 + tg) ^ asw)];
                a[mt][2] = xg[r1 + ((k0 + tg + 4) ^ asw)];
                a[mt][3] = xg[r2 + ((k0 + tg + 4) ^ asw)];
            }
            const int kr0 = (k0 + tg) * H;
            const int kr1 = (k0 + tg + 4) * H;
            #pragma unroll
            for (int nt = 0; nt < 8; nt++) {
                const int n = nb1 + nt * 8 + g;
                uint32_t bb0 = s32[OFF_W1 + kr0 + (n ^ bsw)];
                uint32_t bb1 = s32[OFF_W1 + kr1 + (n ^ bsw)];
                mma_tf32(acc[0][nt], a[0][0], a[0][1], a[0][2], a[0][3], bb0, bb1);
                mma_tf32(acc[1][nt], a[1][0], a[1][1], a[1][2], a[1][3], bb0, bb1);
            }
        }
        __syncthreads();   // everyone done reading x before h1 overwrites it

        // ---- h1 = relu(acc + b1) -> smem (tf32, cols 0..127 of x region) ----
        #pragma unroll
        for (int mt = 0; mt < 2; mt++) {
            const int r1 = (group * 32 + mt * 16 + g) * 256;
            const int r2 = (group * 32 + mt * 16 + g + 8) * 256;
            #pragma unroll
            for (int nt = 0; nt < 8; nt++) {
                const int j = (nb1 + nt * 8 + 2 * tg) ^ asw;
                uint2 lo, hi;
                lo.x = f2tf(fmaxf(acc[mt][nt][0] + b1f[nt][0], 0.f));
                lo.y = f2tf(fmaxf(acc[mt][nt][1] + b1f[nt][1], 0.f));
                hi.x = f2tf(fmaxf(acc[mt][nt][2] + b1f[nt][0], 0.f));
                hi.y = f2tf(fmaxf(acc[mt][nt][3] + b1f[nt][1], 0.f));
                *reinterpret_cast<uint2*>(&s32[OFF_X + r1 + j]) = lo;
                *reinterpret_cast<uint2*>(&s32[OFF_X + r2 + j]) = hi;
            }
        }
        __syncthreads();

        // ---- layer 2: C[32 x 32] = H1 @ W2, K=128 ----
        float acc2[2][4][4];
        #pragma unroll
        for (int mt = 0; mt < 2; mt++)
            #pragma unroll
            for (int nt = 0; nt < 4; nt++)
                #pragma unroll
                for (int q = 0; q < 4; q++) acc2[mt][nt][q] = 0.f;

        #pragma unroll 4
        for (int kk = 0; kk < 16; kk++) {
            const int k0 = kk * 8;
            uint32_t a[2][4];
            #pragma unroll
            for (int mt = 0; mt < 2; mt++) {
                const int r1 = (mt * 16 + g) * 256;
                const int r2 = (mt * 16 + g + 8) * 256;
                a[mt][0] = xg[r1 + ((k0 + tg) ^ asw)];
                a[mt][1] = xg[r2 + ((k0 + tg) ^ asw)];
                a[mt][2] = xg[r1 + ((k0 + tg + 4) ^ asw)];
                a[mt][3] = xg[r2 + ((k0 + tg + 4) ^ asw)];
            }
            const int kr0 = (k0 + tg) * H2;
            const int kr1 = (k0 + tg + 4) * H2;
            #pragma unroll
            for (int nt = 0; nt < 4; nt++) {
                const int n = nb2 + nt * 8 + g;
                uint32_t bb0 = s32[OFF_W2 + kr0 + (n ^ bsw)];
                uint32_t bb1 = s32[OFF_W2 + kr1 + (n ^ bsw)];
                mma_tf32(acc2[0][nt], a[0][0], a[0][1], a[0][2], a[0][3], bb0, bb1);
                mma_tf32(acc2[1][nt], a[1][0], a[1][1], a[1][2], a[1][3], bb0, bb1);
            }
        }

        // ---- layer 3: per-thread partial dot with W3, shfl reduce over tg ----
        float p[2][2] = {{0.f, 0.f}, {0.f, 0.f}};
        #pragma unroll
        for (int mt = 0; mt < 2; mt++)
            #pragma unroll
            for (int nt = 0; nt < 4; nt++) {
                p[mt][0] += fmaxf(acc2[mt][nt][0] + b2f[nt][0], 0.f) * w3f[nt][0]
                          + fmaxf(acc2[mt][nt][1] + b2f[nt][1], 0.f) * w3f[nt][1];
                p[mt][1] += fmaxf(acc2[mt][nt][2] + b2f[nt][0], 0.f) * w3f[nt][0]
                          + fmaxf(acc2[mt][nt][3] + b2f[nt][1], 0.f) * w3f[nt][1];
            }
        #pragma unroll
        for (int mt = 0; mt < 2; mt++)
            #pragma unroll
            for (int r = 0; r < 2; r++) {
                p[mt][r] += __shfl_xor_sync(0xffffffffu, p[mt][r], 1);
                p[mt][r] += __shfl_xor_sync(0xffffffffu, p[mt][r], 2);
            }
        if (tg == 0) {
            #pragma unroll
            for (int mt = 0; mt < 2; mt++) {
                part[(group * 32 + mt * 16 + g) * 2 + nhalf]     = p[mt][0];
                part[(group * 32 + mt * 16 + g + 8) * 2 + nhalf] = p[mt][1];
            }
        }
        __syncthreads();

        if (tid < TILE_E) {
            long long eid = e0 + tid;
            if (eid < (long long)E)
                out[eid] = part[tid * 2] + part[tid * 2 + 1] + b3v;
        }
        // next iteration's sidx-write is followed by a __syncthreads, and x/part
        // rewrites happen only after further barriers -> no WAR hazards.
    }
}

extern "C" void kernel_launch(void* const* d_in, const int* in_sizes, int n_in,
                              void* d_out, int out_size)
{
    const float* z  = (const float*)d_in[0];
    const int*   ei = (const int*)d_in[1];
    const float* W1 = (const float*)d_in[2];
    const float* b1 = (const float*)d_in[3];
    const float* W2 = (const float*)d_in[4];
    const float* b2 = (const float*)d_in[5];
    const float* W3 = (const float*)d_in[6];
    const float* b3 = (const float*)d_in[7];
    float* out = (float*)d_out;

    const int E       = in_sizes[1] / 2;
    const int n_nodes = in_sizes[0] / 128;
    const int ntiles  = (E + TILE_E - 1) / TILE_E;
    const int smem_bytes = SMEM_FLOATS * 4;   // 230400 B

    static bool attr_set = false;
    if (!attr_set) {
        cudaFuncSetAttribute(lp_tc, cudaFuncAttributeMaxDynamicSharedMemorySize, smem_bytes);
        attr_set = true;
    }
    int grid = 148;
    if (grid > ntiles) grid = ntiles;
    lp_tc<<<grid, 128, smem_bytes>>>(z, ei, W1, b1, W2, b2, W3, b3, out, E, n_nodes, ntiles);
}

// round 5
// speedup vs baseline: 2.3909x; 1.3902x over previous
#include <cuda_runtime.h>
#include <cstdint>

#define TWO_D 256
#define H     128
#define H2    64
#define TILE_E 64

// dynamic smem layout (u32 indices)
#define OFF_W1   0                        // 32768 u32: W1 fragment-major
#define OFF_W2   32768                    // 8192 u32: W2 fragment-major
#define OFF_X    40960                    // 64*256 u32: x (later h1), row-major swizzled
#define OFF_IDX  57344                    // 128 int
#define OFF_PART 57472                    // 64*4 float
#define SMEM_U32 57728                    // * 4B = 230912 B

__device__ __forceinline__ uint32_t f2tf(float f) {
    uint32_t r;
    asm("cvt.rna.tf32.f32 %0, %1;" : "=r"(r) : "f"(f));
    return r;
}

__device__ __forceinline__ void mma_tf32(float c[4],
    uint32_t a0, uint32_t a1, uint32_t a2, uint32_t a3,
    uint32_t b0, uint32_t b1)
{
    asm volatile("mma.sync.aligned.m16n8k8.row.col.f32.tf32.tf32.f32 "
        "{%0,%1,%2,%3}, {%4,%5,%6,%7}, {%8,%9}, {%0,%1,%2,%3};"
        : "+f"(c[0]), "+f"(c[1]), "+f"(c[2]), "+f"(c[3])
        : "r"(a0), "r"(a1), "r"(a2), "r"(a3), "r"(b0), "r"(b1));
}

extern __shared__ float smem[];

__global__ void __launch_bounds__(256, 1) lp_tc(
    const float* __restrict__ z,
    const int*   __restrict__ ei,
    const float* __restrict__ W1,
    const float* __restrict__ b1,
    const float* __restrict__ W2,
    const float* __restrict__ b2,
    const float* __restrict__ W3,
    const float* __restrict__ b3,
    float* __restrict__ out,
    int E, int n_nodes, int ntiles)
{
    const int tid  = threadIdx.x;
    const int lane = tid & 31;
    const int wid  = tid >> 5;
    const int tg   = lane & 3;
    const int g    = lane >> 2;
    uint32_t* s32 = reinterpret_cast<uint32_t*>(smem);
    int*   sidx = reinterpret_cast<int*>(smem + OFF_IDX);
    float* part = smem + OFF_PART;

    // ---- one-time: W1 -> smem, fragment-major ----
    // element (k,n): kk=k>>3, tg=k&3, t=(k>>2)&1; nq=n>>5, g=n&7, ntl=(n>>3)&3
    // flat = (((kk*4+nq)*2 + (ntl>>1))*32 + g*4+tg)*4 + (ntl&1)*2 + t
    for (int i = tid; i < TWO_D * H; i += 256) {
        int k = i >> 7, n = i & 127;
        int kk = k >> 3, ktg = k & 3, t = (k >> 2) & 1;
        int nq = n >> 5, ng = n & 7, ntl = (n >> 3) & 3;
        int flat = ((((kk * 4 + nq) * 2 + (ntl >> 1)) * 32) + ng * 4 + ktg) * 4 + (ntl & 1) * 2 + t;
        s32[OFF_W1 + flat] = f2tf(__ldg(W1 + i));
    }
    // ---- one-time: W2 -> smem, fragment-major ----
    // element (k,m): kk=k>>3 (0..15); nq=m>>4, g=m&7, ntl=(m>>3)&1
    // flat = ((kk*4+nq)*32 + g*4+tg)*4 + ntl*2 + t
    for (int i = tid; i < H * H2; i += 256) {
        int k = i >> 6, m = i & 63;
        int kk = k >> 3, ktg = k & 3, t = (k >> 2) & 1;
        int nq = m >> 4, ng = m & 7, ntl = (m >> 3) & 1;
        int flat = (((kk * 4 + nq) * 32) + ng * 4 + ktg) * 4 + ntl * 2 + t;
        s32[OFF_W2 + flat] = f2tf(__ldg(W2 + i));
    }

    // warp roles: group = edge half (32 edges), nq = N quarter
    const int group = wid >> 2;
    const int nq    = wid & 3;
    const int nb1 = nq * 32;   // layer-1 col base (32 cols per warp)
    const int nb2 = nq * 16;   // layer-2 col base (16 cols per warp)

    // cached bias / W3 fragments
    float b1f[4][2], b2f[2][2], w3f[2][2];
    #pragma unroll
    for (int nt = 0; nt < 4; nt++) {
        b1f[nt][0] = __ldg(b1 + nb1 + nt * 8 + 2 * tg);
        b1f[nt][1] = __ldg(b1 + nb1 + nt * 8 + 2 * tg + 1);
    }
    #pragma unroll
    for (int nt = 0; nt < 2; nt++) {
        b2f[nt][0] = __ldg(b2 + nb2 + nt * 8 + 2 * tg);
        b2f[nt][1] = __ldg(b2 + nb2 + nt * 8 + 2 * tg + 1);
        w3f[nt][0] = __ldg(W3 + nb2 + nt * 8 + 2 * tg);
        w3f[nt][1] = __ldg(W3 + nb2 + nt * 8 + 2 * tg + 1);
    }
    const float b3v = __ldg(b3);
    __syncthreads();

    const int asw = g << 2;    // x swizzle for A-fragment rows (row&7 == g)

    for (int tile = blockIdx.x; tile < ntiles; tile += gridDim.x) {
        const long long e0 = (long long)tile * TILE_E;

        // ---- stage edge indices (threads 0..127) ----
        if (tid < 128) {
            long long eid = e0 + (tid & 63);
            if (eid >= (long long)E) eid = (long long)E - 1;
            int v = (tid < 64) ? __ldg(ei + eid) : __ldg(ei + (long long)E + eid);
            sidx[tid] = min(max(v, 0), n_nodes - 1);
        }
        __syncthreads();

        // ---- gather x = [z_src | z_dst] -> smem tf32, swizzle k ^ ((e&7)<<2) ----
        for (int i = tid; i < TILE_E * 64; i += 256) {   // 64 float4 per edge
            int e = i >> 6;
            int c = i & 63;
            int node = sidx[(c < 32) ? e : (64 + e)];
            float4 v = __ldg((const float4*)(z + (size_t)node * 128) + (c & 31));
            int kbase = ((c & 31) << 2) + ((c >> 5) << 7);
            uint4 t; t.x = f2tf(v.x); t.y = f2tf(v.y); t.z = f2tf(v.z); t.w = f2tf(v.w);
            *reinterpret_cast<uint4*>(&s32[OFF_X + e * 256 + (kbase ^ ((e & 7) << 2))]) = t;
        }
        __syncthreads();

        const uint32_t* xg = &s32[OFF_X + (group * 32) * 256];

        // ---- layer 1: C[32 edges x 32 cols] = X @ W1, K=256 ----
        float acc[2][4][4];
        #pragma unroll
        for (int mt = 0; mt < 2; mt++)
            #pragma unroll
            for (int nt = 0; nt < 4; nt++)
                #pragma unroll
                for (int q = 0; q < 4; q++) acc[mt][nt][q] = 0.f;

        #pragma unroll 4
        for (int kk = 0; kk < 32; kk++) {
            const int k0 = kk * 8;
            uint32_t a[2][4];
            #pragma unroll
            for (int mt = 0; mt < 2; mt++) {
                const int r1 = (mt * 16 + g) * 256;
                const int r2 = (mt * 16 + g + 8) * 256;
                a[mt][0] = xg[r1 + ((k0 + tg) ^ asw)];
                a[mt][1] = xg[r2 + ((k0 + tg) ^ asw)];
                a[mt][2] = xg[r1 + ((k0 + tg + 4) ^ asw)];
                a[mt][3] = xg[r2 + ((k0 + tg + 4) ^ asw)];
            }
            const uint4 bfA = *reinterpret_cast<const uint4*>(
                &s32[OFF_W1 + ((((kk * 4 + nq) * 2 + 0) * 32) + lane) * 4]);
            const uint4 bfB = *reinterpret_cast<const uint4*>(
                &s32[OFF_W1 + ((((kk * 4 + nq) * 2 + 1) * 32) + lane) * 4]);
            #pragma unroll
            for (int mt = 0; mt < 2; mt++) {
                mma_tf32(acc[mt][0], a[mt][0], a[mt][1], a[mt][2], a[mt][3], bfA.x, bfA.y);
                mma_tf32(acc[mt][1], a[mt][0], a[mt][1], a[mt][2], a[mt][3], bfA.z, bfA.w);
                mma_tf32(acc[mt][2], a[mt][0], a[mt][1], a[mt][2], a[mt][3], bfB.x, bfB.y);
                mma_tf32(acc[mt][3], a[mt][0], a[mt][1], a[mt][2], a[mt][3], bfB.z, bfB.w);
            }
        }
        __syncthreads();   // everyone done reading x before h1 overwrites it

        // ---- h1 = relu(acc + b1) -> x region (tf32, cols 0..127) ----
        #pragma unroll
        for (int mt = 0; mt < 2; mt++) {
            const int r1 = (group * 32 + mt * 16 + g) * 256;
            const int r2 = (group * 32 + mt * 16 + g + 8) * 256;
            #pragma unroll
            for (int nt = 0; nt < 4; nt++) {
                const int j = (nb1 + nt * 8 + 2 * tg) ^ asw;
                uint2 lo, hi;
                lo.x = f2tf(fmaxf(acc[mt][nt][0] + b1f[nt][0], 0.f));
                lo.y = f2tf(fmaxf(acc[mt][nt][1] + b1f[nt][1], 0.f));
                hi.x = f2tf(fmaxf(acc[mt][nt][2] + b1f[nt][0], 0.f));
                hi.y = f2tf(fmaxf(acc[mt][nt][3] + b1f[nt][1], 0.f));
                *reinterpret_cast<uint2*>(&s32[OFF_X + r1 + j]) = lo;
                *reinterpret_cast<uint2*>(&s32[OFF_X + r2 + j]) = hi;
            }
        }
        __syncthreads();

        // ---- layer 2: C[32 x 16] = H1 @ W2, K=128 ----
        float acc2[2][2][4];
        #pragma unroll
        for (int mt = 0; mt < 2; mt++)
            #pragma unroll
            for (int nt = 0; nt < 2; nt++)
                #pragma unroll
                for (int q = 0; q < 4; q++) acc2[mt][nt][q] = 0.f;

        #pragma unroll 4
        for (int kk = 0; kk < 16; kk++) {
            const int k0 = kk * 8;
            uint32_t a[2][4];
            #pragma unroll
            for (int mt = 0; mt < 2; mt++) {
                const int r1 = (mt * 16 + g) * 256;
                const int r2 = (mt * 16 + g + 8) * 256;
                a[mt][0] = xg[r1 + ((k0 + tg) ^ asw)];
                a[mt][1] = xg[r2 + ((k0 + tg) ^ asw)];
                a[mt][2] = xg[r1 + ((k0 + tg + 4) ^ asw)];
                a[mt][3] = xg[r2 + ((k0 + tg + 4) ^ asw)];
            }
            const uint4 bf = *reinterpret_cast<const uint4*>(
                &s32[OFF_W2 + (((kk * 4 + nq) * 32) + lane) * 4]);
            #pragma unroll
            for (int mt = 0; mt < 2; mt++) {
                mma_tf32(acc2[mt][0], a[mt][0], a[mt][1], a[mt][2], a[mt][3], bf.x, bf.y);
                mma_tf32(acc2[mt][1], a[mt][0], a[mt][1], a[mt][2], a[mt][3], bf.z, bf.w);
            }
        }

        // ---- layer 3: partial dot with W3; shfl reduce over tg; combine via smem ----
        float p[2][2] = {{0.f, 0.f}, {0.f, 0.f}};
        #pragma unroll
        for (int mt = 0; mt < 2; mt++)
            #pragma unroll
            for (int nt = 0; nt < 2; nt++) {
                p[mt][0] += fmaxf(acc2[mt][nt][0] + b2f[nt][0], 0.f) * w3f[nt][0]
                          + fmaxf(acc2[mt][nt][1] + b2f[nt][1], 0.f) * w3f[nt][1];
                p[mt][1] += fmaxf(acc2[mt][nt][2] + b2f[nt][0], 0.f) * w3f[nt][0]
                          + fmaxf(acc2[mt][nt][3] + b2f[nt][1], 0.f) * w3f[nt][1];
            }
        #pragma unroll
        for (int mt = 0; mt < 2; mt++)
            #pragma unroll
            for (int r = 0; r < 2; r++) {
                p[mt][r] += __shfl_xor_sync(0xffffffffu, p[mt][r], 1);
                p[mt][r] += __shfl_xor_sync(0xffffffffu, p[mt][r], 2);
            }
        if (tg == 0) {
            #pragma unroll
            for (int mt = 0; mt < 2; mt++) {
                part[(group * 32 + mt * 16 + g) * 4 + nq]     = p[mt][0];
                part[(group * 32 + mt * 16 + g + 8) * 4 + nq] = p[mt][1];
            }
        }
        __syncthreads();

        if (tid < TILE_E) {
            long long eid = e0 + tid;
            if (eid < (long long)E)
                out[eid] = part[tid * 4] + part[tid * 4 + 1]
                         + part[tid * 4 + 2] + part[tid * 4 + 3] + b3v;
        }
        // x is only rewritten after the gather that follows the next __syncthreads.
    }
}

extern "C" void kernel_launch(void* const* d_in, const int* in_sizes, int n_in,
                              void* d_out, int out_size)
{
    const float* z  = (const float*)d_in[0];
    const int*   ei = (const int*)d_in[1];
    const float* W1 = (const float*)d_in[2];
    const float* b1 = (const float*)d_in[3];
    const float* W2 = (const float*)d_in[4];
    const float* b2 = (const float*)d_in[5];
    const float* W3 = (const float*)d_in[6];
    const float* b3 = (const float*)d_in[7];
    float* out = (float*)d_out;

    const int E       = in_sizes[1] / 2;
    const int n_nodes = in_sizes[0] / 128;
    const int ntiles  = (E + TILE_E - 1) / TILE_E;
    const int smem_bytes = SMEM_U32 * 4;   // 230912 B

    static bool attr_set = false;
    if (!attr_set) {
        cudaFuncSetAttribute(lp_tc, cudaFuncAttributeMaxDynamicSharedMemorySize, smem_bytes);
        attr_set = true;
    }
    int grid = 148;
    if (grid > ntiles) grid = ntiles;
    lp_tc<<<grid, 256, smem_bytes>>>(z, ei, W1, b1, W2, b2, W3, b3, out, E, n_nodes, ntiles);
}

// round 6
// speedup vs baseline: 2.6180x; 1.0950x over previous
#include <cuda_runtime.h>
#include <cstdint>

#define TWO_D 256
#define H     128
#define H2    64
#define TILE_E 64
#define NTHREADS 512

// dynamic smem layout (u32 indices)
#define OFF_W1   0                        // 32768 u32: W1 fragment-major
#define OFF_W2   32768                    // 8192 u32: W2 fragment-major
#define OFF_X    40960                    // 64*256 u32: x (later h1), row-major swizzled
#define OFF_IDX  57344                    // 128 int
#define OFF_PART 57472                    // 64*4 float
#define SMEM_U32 57728                    // * 4B = 230912 B

__device__ __forceinline__ uint32_t f2tf(float f) {
    uint32_t r;
    asm("cvt.rna.tf32.f32 %0, %1;" : "=r"(r) : "f"(f));
    return r;
}

__device__ __forceinline__ void mma_tf32(float c[4],
    uint32_t a0, uint32_t a1, uint32_t a2, uint32_t a3,
    uint32_t b0, uint32_t b1)
{
    asm volatile("mma.sync.aligned.m16n8k8.row.col.f32.tf32.tf32.f32 "
        "{%0,%1,%2,%3}, {%4,%5,%6,%7}, {%8,%9}, {%0,%1,%2,%3};"
        : "+f"(c[0]), "+f"(c[1]), "+f"(c[2]), "+f"(c[3])
        : "r"(a0), "r"(a1), "r"(a2), "r"(a3), "r"(b0), "r"(b1));
}

extern __shared__ float smem[];

__global__ void __launch_bounds__(NTHREADS, 1) lp_tc(
    const float* __restrict__ z,
    const int*   __restrict__ ei,
    const float* __restrict__ W1,
    const float* __restrict__ b1,
    const float* __restrict__ W2,
    const float* __restrict__ b2,
    const float* __restrict__ W3,
    const float* __restrict__ b3,
    float* __restrict__ out,
    int E, int n_nodes, int ntiles)
{
    const int tid  = threadIdx.x;
    const int lane = tid & 31;
    const int wid  = tid >> 5;
    const int tg   = lane & 3;
    const int g    = lane >> 2;
    uint32_t* s32 = reinterpret_cast<uint32_t*>(smem);
    int*   sidx = reinterpret_cast<int*>(smem + OFF_IDX);
    float* part = smem + OFF_PART;

    // ---- one-time: W1 -> smem, fragment-major (layout identical to R5) ----
    for (int i = tid; i < TWO_D * H; i += NTHREADS) {
        int k = i >> 7, n = i & 127;
        int kk = k >> 3, ktg = k & 3, t = (k >> 2) & 1;
        int nqq = n >> 5, ng = n & 7, ntl = (n >> 3) & 3;
        int flat = ((((kk * 4 + nqq) * 2 + (ntl >> 1)) * 32) + ng * 4 + ktg) * 4 + (ntl & 1) * 2 + t;
        s32[OFF_W1 + flat] = f2tf(__ldg(W1 + i));
    }
    for (int i = tid; i < H * H2; i += NTHREADS) {
        int k = i >> 6, m = i & 63;
        int kk = k >> 3, ktg = k & 3, t = (k >> 2) & 1;
        int nqq = m >> 4, ng = m & 7, ntl = (m >> 3) & 1;
        int flat = (((kk * 4 + nqq) * 32) + ng * 4 + ktg) * 4 + ntl * 2 + t;
        s32[OFF_W2 + flat] = f2tf(__ldg(W2 + i));
    }

    // warp roles: 16 warps = 4 M-tiles (16 edges each) x 4 N-quarters
    const int mtile = wid >> 2;
    const int nq    = wid & 3;
    const int nb1 = nq * 32;   // layer-1 col base
    const int nb2 = nq * 16;   // layer-2 col base

    float b1f[4][2], b2f[2][2], w3f[2][2];
    #pragma unroll
    for (int nt = 0; nt < 4; nt++) {
        b1f[nt][0] = __ldg(b1 + nb1 + nt * 8 + 2 * tg);
        b1f[nt][1] = __ldg(b1 + nb1 + nt * 8 + 2 * tg + 1);
    }
    #pragma unroll
    for (int nt = 0; nt < 2; nt++) {
        b2f[nt][0] = __ldg(b2 + nb2 + nt * 8 + 2 * tg);
        b2f[nt][1] = __ldg(b2 + nb2 + nt * 8 + 2 * tg + 1);
        w3f[nt][0] = __ldg(W3 + nb2 + nt * 8 + 2 * tg);
        w3f[nt][1] = __ldg(W3 + nb2 + nt * 8 + 2 * tg + 1);
    }
    const float b3v = __ldg(b3);
    __syncthreads();

    const int asw = g << 2;    // x swizzle for A rows (row&7 == g)
    const int r1o = g * 256;
    const int r2o = (g + 8) * 256;

    for (int tile = blockIdx.x; tile < ntiles; tile += gridDim.x) {
        const long long e0 = (long long)tile * TILE_E;

        // ---- stage edge indices ----
        if (tid < 128) {
            long long eid = e0 + (tid & 63);
            if (eid >= (long long)E) eid = (long long)E - 1;
            int v = (tid < 64) ? __ldg(ei + eid) : __ldg(ei + (long long)E + eid);
            sidx[tid] = min(max(v, 0), n_nodes - 1);
        }
        __syncthreads();

        // ---- gather x = [z_src | z_dst] -> smem tf32, swizzle k ^ ((e&7)<<2) ----
        for (int i = tid; i < TILE_E * 64; i += NTHREADS) {
            int e = i >> 6;
            int c = i & 63;
            int node = sidx[(c < 32) ? e : (64 + e)];
            float4 v = __ldg((const float4*)(z + (size_t)node * 128) + (c & 31));
            int kbase = ((c & 31) << 2) + ((c >> 5) << 7);
            uint4 t; t.x = f2tf(v.x); t.y = f2tf(v.y); t.z = f2tf(v.z); t.w = f2tf(v.w);
            *reinterpret_cast<uint4*>(&s32[OFF_X + e * 256 + (kbase ^ ((e & 7) << 2))]) = t;
        }
        __syncthreads();

        const uint32_t* xm = &s32[OFF_X + (mtile * 16) * 256];

        // ---- layer 1: C[16 edges x 32 cols] = X @ W1, K=256 ----
        float acc[4][4];
        #pragma unroll
        for (int nt = 0; nt < 4; nt++)
            #pragma unroll
            for (int q = 0; q < 4; q++) acc[nt][q] = 0.f;

        #pragma unroll 8
        for (int kk = 0; kk < 32; kk++) {
            const int k0 = kk * 8;
            uint32_t a0 = xm[r1o + ((k0 + tg) ^ asw)];
            uint32_t a1 = xm[r2o + ((k0 + tg) ^ asw)];
            uint32_t a2 = xm[r1o + ((k0 + tg + 4) ^ asw)];
            uint32_t a3 = xm[r2o + ((k0 + tg + 4) ^ asw)];
            const uint4 bfA = *reinterpret_cast<const uint4*>(
                &s32[OFF_W1 + ((((kk * 4 + nq) * 2 + 0) * 32) + lane) * 4]);
            const uint4 bfB = *reinterpret_cast<const uint4*>(
                &s32[OFF_W1 + ((((kk * 4 + nq) * 2 + 1) * 32) + lane) * 4]);
            mma_tf32(acc[0], a0, a1, a2, a3, bfA.x, bfA.y);
            mma_tf32(acc[1], a0, a1, a2, a3, bfA.z, bfA.w);
            mma_tf32(acc[2], a0, a1, a2, a3, bfB.x, bfB.y);
            mma_tf32(acc[3], a0, a1, a2, a3, bfB.z, bfB.w);
        }
        __syncthreads();   // all reads of x done before h1 overwrites it

        // ---- h1 = relu(acc + b1) -> x region (tf32, cols 0..127) ----
        {
            const int rw1 = (mtile * 16 + g) * 256;
            const int rw2 = (mtile * 16 + g + 8) * 256;
            #pragma unroll
            for (int nt = 0; nt < 4; nt++) {
                const int j = (nb1 + nt * 8 + 2 * tg) ^ asw;
                uint2 lo, hi;
                lo.x = f2tf(fmaxf(acc[nt][0] + b1f[nt][0], 0.f));
                lo.y = f2tf(fmaxf(acc[nt][1] + b1f[nt][1], 0.f));
                hi.x = f2tf(fmaxf(acc[nt][2] + b1f[nt][0], 0.f));
                hi.y = f2tf(fmaxf(acc[nt][3] + b1f[nt][1], 0.f));
                *reinterpret_cast<uint2*>(&s32[OFF_X + rw1 + j]) = lo;
                *reinterpret_cast<uint2*>(&s32[OFF_X + rw2 + j]) = hi;
            }
        }
        __syncthreads();

        // ---- layer 2: C[16 x 16] = H1 @ W2, K=128 ----
        float acc2[2][4];
        #pragma unroll
        for (int nt = 0; nt < 2; nt++)
            #pragma unroll
            for (int q = 0; q < 4; q++) acc2[nt][q] = 0.f;

        #pragma unroll 8
        for (int kk = 0; kk < 16; kk++) {
            const int k0 = kk * 8;
            uint32_t a0 = xm[r1o + ((k0 + tg) ^ asw)];
            uint32_t a1 = xm[r2o + ((k0 + tg) ^ asw)];
            uint32_t a2 = xm[r1o + ((k0 + tg + 4) ^ asw)];
            uint32_t a3 = xm[r2o + ((k0 + tg + 4) ^ asw)];
            const uint4 bf = *reinterpret_cast<const uint4*>(
                &s32[OFF_W2 + (((kk * 4 + nq) * 32) + lane) * 4]);
            mma_tf32(acc2[0], a0, a1, a2, a3, bf.x, bf.y);
            mma_tf32(acc2[1], a0, a1, a2, a3, bf.z, bf.w);
        }

        // ---- layer 3: partial dot with W3; shfl reduce over tg; combine via smem ----
        float p0 = 0.f, p1 = 0.f;
        #pragma unroll
        for (int nt = 0; nt < 2; nt++) {
            p0 += fmaxf(acc2[nt][0] + b2f[nt][0], 0.f) * w3f[nt][0]
                + fmaxf(acc2[nt][1] + b2f[nt][1], 0.f) * w3f[nt][1];
            p1 += fmaxf(acc2[nt][2] + b2f[nt][0], 0.f) * w3f[nt][0]
                + fmaxf(acc2[nt][3] + b2f[nt][1], 0.f) * w3f[nt][1];
        }
        p0 += __shfl_xor_sync(0xffffffffu, p0, 1);
        p0 += __shfl_xor_sync(0xffffffffu, p0, 2);
        p1 += __shfl_xor_sync(0xffffffffu, p1, 1);
        p1 += __shfl_xor_sync(0xffffffffu, p1, 2);
        if (tg == 0) {
            part[(mtile * 16 + g) * 4 + nq]     = p0;
            part[(mtile * 16 + g + 8) * 4 + nq] = p1;
        }
        __syncthreads();

        if (tid < TILE_E) {
            long long eid = e0 + tid;
            if (eid < (long long)E)
                out[eid] = part[tid * 4] + part[tid * 4 + 1]
                         + part[tid * 4 + 2] + part[tid * 4 + 3] + b3v;
        }
        // x region only rewritten after the next __syncthreads -> no WAR hazard.
    }
}

extern "C" void kernel_launch(void* const* d_in, const int* in_sizes, int n_in,
                              void* d_out, int out_size)
{
    const float* z  = (const float*)d_in[0];
    const int*   ei = (const int*)d_in[1];
    const float* W1 = (const float*)d_in[2];
    const float* b1 = (const float*)d_in[3];
    const float* W2 = (const float*)d_in[4];
    const float* b2 = (const float*)d_in[5];
    const float* W3 = (const float*)d_in[6];
    const float* b3 = (const float*)d_in[7];
    float* out = (float*)d_out;

    const int E       = in_sizes[1] / 2;
    const int n_nodes = in_sizes[0] / 128;
    const int ntiles  = (E + TILE_E - 1) / TILE_E;
    const int smem_bytes = SMEM_U32 * 4;   // 230912 B

    static bool attr_set = false;
    if (!attr_set) {
        cudaFuncSetAttribute(lp_tc, cudaFuncAttributeMaxDynamicSharedMemorySize, smem_bytes);
        attr_set = true;
    }
    int grid = 148;
    if (grid > ntiles) grid = ntiles;
    lp_tc<<<grid, NTHREADS, smem_bytes>>>(z, ei, W1, b1, W2, b2, W3, b3, out, E, n_nodes, ntiles);
}

// round 8
// speedup vs baseline: 2.7723x; 1.0589x over previous
#include <cuda_runtime.h>
#include <cstdint>

#define TILE_E   96
#define NTHREADS 768

// smem layout in 4-byte words
#define W1F    0        // 32768 : W1 fragment-major tf32
#define XA_F   32768    // 12288 : X half A (96 x 128 f32, 16B-swizzled)
#define XB_F   45056    // 12288 : X half B
#define SIDX_F 57344    // 192 ints (96 src, 96 dst)
#define PART_F 57536    // 384 floats
#define SMEM_W 57920    // * 4 = 231680 B

__device__ __align__(16) unsigned g_w2frag[128 * 64];   // W2 fragment-major tf32, L2-resident

__device__ __forceinline__ uint32_t f2tf(float f) {
    uint32_t r; asm("cvt.rna.tf32.f32 %0, %1;" : "=r"(r) : "f"(f)); return r;
}
__device__ __forceinline__ uint32_t smem_u32(const void* p) {
    uint32_t a; asm("{ .reg .u64 t; cvta.to.shared.u64 t, %1; cvt.u32.u64 %0, t; }" : "=r"(a) : "l"(p));
    return a;
}
__device__ __forceinline__ void mma_tf32(float c[4],
    uint32_t a0, uint32_t a1, uint32_t a2, uint32_t a3, uint32_t b0, uint32_t b1)
{
    asm volatile("mma.sync.aligned.m16n8k8.row.col.f32.tf32.tf32.f32 "
        "{%0,%1,%2,%3}, {%4,%5,%6,%7}, {%8,%9}, {%0,%1,%2,%3};"
        : "+f"(c[0]), "+f"(c[1]), "+f"(c[2]), "+f"(c[3])
        : "r"(a0), "r"(a1), "r"(a2), "r"(a3), "r"(b0), "r"(b1));
}
__device__ __forceinline__ void cpa16(uint32_t s, const void* g) {
    asm volatile("cp.async.cg.shared.global [%0], [%1], 16;" :: "r"(s), "l"(g));
}
#define CPA_COMMIT() asm volatile("cp.async.commit_group;" ::: "memory")
#define CPA_WAIT(n)  asm volatile("cp.async.wait_group %0;" :: "n"(n) : "memory")

__global__ void repack_w2(const float* __restrict__ W2) {
    int i = blockIdx.x * blockDim.x + threadIdx.x;   // i over W2[k][m], k<128, m<64
    if (i < 128 * 64) {
        int k = i >> 6, m = i & 63;
        int kk = k >> 3, ktg = k & 3, t = (k >> 2) & 1;
        int nqq = m >> 4, ng = m & 7, ntl = (m >> 3) & 1;
        int flat = (((kk * 4 + nqq) * 32) + ng * 4 + ktg) * 4 + ntl * 2 + t;
        g_w2frag[flat] = f2tf(__ldg(W2 + i));
    }
}

// one 16-k-step MMA segment over a 96x128 staged half
__device__ __forceinline__ void mma_seg(const float* __restrict__ xm,
                                        const uint32_t* __restrict__ w1f,
                                        int kkbase, int nq, int lane, int g, int tg,
                                        float acc[4][4])
{
    const int asw = g << 2;
    #pragma unroll 4
    for (int kk2 = 0; kk2 < 16; kk2++) {
        const int kk = kkbase + kk2;
        const int k0 = kk2 * 8;
        uint32_t a0 = f2tf(xm[g * 128 + ((k0 + tg) ^ asw)]);
        uint32_t a1 = f2tf(xm[(g + 8) * 128 + ((k0 + tg) ^ asw)]);
        uint32_t a2 = f2tf(xm[g * 128 + ((k0 + tg + 4) ^ asw)]);
        uint32_t a3 = f2tf(xm[(g + 8) * 128 + ((k0 + tg + 4) ^ asw)]);
        const uint4 bfA = *reinterpret_cast<const uint4*>(
            w1f + ((((kk * 4 + nq) * 2 + 0) * 32) + lane) * 4);
        const uint4 bfB = *reinterpret_cast<const uint4*>(
            w1f + ((((kk * 4 + nq) * 2 + 1) * 32) + lane) * 4);
        mma_tf32(acc[0], a0, a1, a2, a3, bfA.x, bfA.y);
        mma_tf32(acc[1], a0, a1, a2, a3, bfA.z, bfA.w);
        mma_tf32(acc[2], a0, a1, a2, a3, bfB.x, bfB.y);
        mma_tf32(acc[3], a0, a1, a2, a3, bfB.z, bfB.w);
    }
}

extern __shared__ float smem[];

__global__ void __launch_bounds__(NTHREADS, 1) lp_tc(
    const float* __restrict__ z,
    const int*   __restrict__ ei,
    const float* __restrict__ W1,
    const float* __restrict__ b1,
    const float* __restrict__ b2,
    const float* __restrict__ W3,
    const float* __restrict__ b3,
    float* __restrict__ out,
    int E, int n_nodes, int ntiles)
{
    const int tid  = threadIdx.x;
    const int lane = tid & 31;
    const int wid  = tid >> 5;
    const int tg   = lane & 3;
    const int g    = lane >> 2;
    uint32_t* s32 = reinterpret_cast<uint32_t*>(smem);
    int* sidx = reinterpret_cast<int*>(smem + SIDX_F);
    float* part = smem + PART_F;
    const uint32_t smb = smem_u32(smem);

    // ---- one-time: W1 -> smem fragment-major (validated R5/R6 layout) ----
    for (int i = tid; i < 256 * 128; i += NTHREADS) {   // i over W1[k][n]
        int k = i >> 7, n = i & 127;
        int kk = k >> 3, ktg = k & 3, t = (k >> 2) & 1;
        int nqq = n >> 5, ng = n & 7, ntl = (n >> 3) & 3;
        int flat = ((((kk * 4 + nqq) * 2 + (ntl >> 1)) * 32) + ng * 4 + ktg) * 4 + (ntl & 1) * 2 + t;
        s32[W1F + flat] = f2tf(__ldg(W1 + i));
    }

    // warp roles: 24 warps = 6 M-groups (16 edges) x 4 N-quarters
    const int mtile = wid >> 2;
    const int nq    = wid & 3;
    const int nb1 = nq * 32;
    const int nb2 = nq * 16;

    float b1f[4][2], b2f[2][2], w3f[2][2];
    #pragma unroll
    for (int nt = 0; nt < 4; nt++) {
        b1f[nt][0] = __ldg(b1 + nb1 + nt * 8 + 2 * tg);
        b1f[nt][1] = __ldg(b1 + nb1 + nt * 8 + 2 * tg + 1);
    }
    #pragma unroll
    for (int nt = 0; nt < 2; nt++) {
        b2f[nt][0] = __ldg(b2 + nb2 + nt * 8 + 2 * tg);
        b2f[nt][1] = __ldg(b2 + nb2 + nt * 8 + 2 * tg + 1);
        w3f[nt][0] = __ldg(W3 + nb2 + nt * 8 + 2 * tg);
        w3f[nt][1] = __ldg(W3 + nb2 + nt * 8 + 2 * tg + 1);
    }
    const float b3v = __ldg(b3);

    const int ge  = tid >> 3;          // gather: edge 0..95
    const int gq  = tid & 7;           // gather: 16-float quarter 0..7
    const int gsw = (ge & 7) << 2;     // gather swizzle

    uint32_t xa_s = smb + XA_F * 4, xb_s = smb + XB_F * 4;
    float *xa = smem + XA_F, *xb = smem + XB_F;

    // ---- prologue: idx(t0) + src-half(t0) -> XA ----
    {
        if (tid < 192) {
            long long eid = (long long)blockIdx.x * TILE_E + (tid < 96 ? tid : tid - 96);
            if (eid >= (long long)E) eid = (long long)E - 1;
            int v = __ldg(ei + (tid < 96 ? eid : (long long)E + eid));
            sidx[tid] = min(max(v, 0), n_nodes - 1);
        }
        __syncthreads();
        const float* gp = z + (size_t)sidx[ge] * 128 + gq * 16;
        #pragma unroll
        for (int j = 0; j < 4; j++)
            cpa16(xa_s + (ge * 128 + ((gq * 16 + j * 4) ^ gsw)) * 4, gp + j * 4);
        CPA_COMMIT();
    }

    for (int tile = blockIdx.x; tile < ntiles; tile += gridDim.x) {
        const long long e0 = (long long)tile * TILE_E;
        const int tn = tile + gridDim.x;
        const bool hn = tn < ntiles;

        // prefetch next tile's indices into regs
        int nv = 0;
        if (hn && tid < 192) {
            long long eid = (long long)tn * TILE_E + (tid < 96 ? tid : tid - 96);
            if (eid >= (long long)E) eid = (long long)E - 1;
            nv = __ldg(ei + (tid < 96 ? eid : (long long)E + eid));
            nv = min(max(nv, 0), n_nodes - 1);
        }

        // issue dst-half(t) -> XB
        {
            const float* gp = z + (size_t)sidx[96 + ge] * 128 + gq * 16;
            #pragma unroll
            for (int j = 0; j < 4; j++)
                cpa16(xb_s + (ge * 128 + ((gq * 16 + j * 4) ^ gsw)) * 4, gp + j * 4);
        }
        CPA_COMMIT();

        CPA_WAIT(1);           // src half landed (dst may still be in flight)
        __syncthreads();

        // ---- layer 1, K 0..127 (src half in XA) ----
        float acc[4][4];
        #pragma unroll
        for (int nt = 0; nt < 4; nt++)
            #pragma unroll
            for (int q = 0; q < 4; q++) acc[nt][q] = 0.f;
        mma_seg(xa + (mtile * 16) * 128, s32 + W1F, 0, nq, lane, g, tg, acc);

        CPA_WAIT(0);           // dst half landed
        __syncthreads();

        // ---- layer 1, K 128..255 (dst half in XB) ----
        mma_seg(xb + (mtile * 16) * 128, s32 + W1F, 16, nq, lane, g, tg, acc);

        if (hn && tid < 192) sidx[tid] = nv;
        __syncthreads();       // K2 reads done; sidx(t+1) visible

        // issue src-half(t+1) -> XB (overlaps epilogue + layer 2/3)
        if (hn) {
            const float* gp = z + (size_t)sidx[ge] * 128 + gq * 16;
            #pragma unroll
            for (int j = 0; j < 4; j++)
                cpa16(xb_s + (ge * 128 + ((gq * 16 + j * 4) ^ gsw)) * 4, gp + j * 4);
        }
        CPA_COMMIT();

        // ---- h1 = relu(acc + b1) -> XA (f32; rounded at consumption) ----
        {
            const int rw1 = (mtile * 16 + g) * 128;
            const int rw2 = (mtile * 16 + g + 8) * 128;
            #pragma unroll
            for (int nt = 0; nt < 4; nt++) {
                const int j = (nb1 + nt * 8 + 2 * tg) ^ (g << 2);
                float2 lo, hi;
                lo.x = fmaxf(acc[nt][0] + b1f[nt][0], 0.f);
                lo.y = fmaxf(acc[nt][1] + b1f[nt][1], 0.f);
                hi.x = fmaxf(acc[nt][2] + b1f[nt][0], 0.f);
                hi.y = fmaxf(acc[nt][3] + b1f[nt][1], 0.f);
                *reinterpret_cast<float2*>(xa + rw1 + j) = lo;
                *reinterpret_cast<float2*>(xa + rw2 + j) = hi;
            }
        }
        __syncthreads();

        // ---- layer 2: C[16 x 16] = H1 @ W2, K=128; W2 frags streamed from L2 ----
        float acc2[2][4];
        #pragma unroll
        for (int nt = 0; nt < 2; nt++)
            #pragma unroll
            for (int q = 0; q < 4; q++) acc2[nt][q] = 0.f;
        {
            const float* xm = xa + (mtile * 16) * 128;
            const int asw = g << 2;
            #pragma unroll 4
            for (int kk = 0; kk < 16; kk++) {
                const int k0 = kk * 8;
                uint32_t a0 = f2tf(xm[g * 128 + ((k0 + tg) ^ asw)]);
                uint32_t a1 = f2tf(xm[(g + 8) * 128 + ((k0 + tg) ^ asw)]);
                uint32_t a2 = f2tf(xm[g * 128 + ((k0 + tg + 4) ^ asw)]);
                uint32_t a3 = f2tf(xm[(g + 8) * 128 + ((k0 + tg + 4) ^ asw)]);
                const uint4 bf = __ldg(reinterpret_cast<const uint4*>(
                    g_w2frag + (((kk * 4 + nq) * 32) + lane) * 4));
                mma_tf32(acc2[0], a0, a1, a2, a3, bf.x, bf.y);
                mma_tf32(acc2[1], a0, a1, a2, a3, bf.z, bf.w);
            }
        }

        // ---- layer 3: dot with W3, shfl reduce, combine ----
        float p0 = 0.f, p1 = 0.f;
        #pragma unroll
        for (int nt = 0; nt < 2; nt++) {
            p0 += fmaxf(acc2[nt][0] + b2f[nt][0], 0.f) * w3f[nt][0]
                + fmaxf(acc2[nt][1] + b2f[nt][1], 0.f) * w3f[nt][1];
            p1 += fmaxf(acc2[nt][2] + b2f[nt][0], 0.f) * w3f[nt][0]
                + fmaxf(acc2[nt][3] + b2f[nt][1], 0.f) * w3f[nt][1];
        }
        p0 += __shfl_xor_sync(0xffffffffu, p0, 1);
        p0 += __shfl_xor_sync(0xffffffffu, p0, 2);
        p1 += __shfl_xor_sync(0xffffffffu, p1, 1);
        p1 += __shfl_xor_sync(0xffffffffu, p1, 2);
        if (tg == 0) {
            part[(mtile * 16 + g) * 4 + nq]     = p0;
            part[(mtile * 16 + g + 8) * 4 + nq] = p1;
        }
        __syncthreads();

        if (tid < TILE_E) {
            long long eid = e0 + tid;
            if (eid < (long long)E)
                out[eid] = part[tid * 4] + part[tid * 4 + 1]
                         + part[tid * 4 + 2] + part[tid * 4 + 3] + b3v;
        }

        // rotate buffers: XB now holds src(t+1)
        { float* tf = xa; xa = xb; xb = tf; uint32_t ts = xa_s; xa_s = xb_s; xb_s = ts; }
    }
}

extern "C" void kernel_launch(void* const* d_in, const int* in_sizes, int n_in,
                              void* d_out, int out_size)
{
    const float* z  = (const float*)d_in[0];
    const int*   ei = (const int*)d_in[1];
    const float* W1 = (const float*)d_in[2];
    const float* b1 = (const float*)d_in[3];
    const float* W2 = (const float*)d_in[4];
    const float* b2 = (const float*)d_in[5];
    const float* W3 = (const float*)d_in[6];
    const float* b3 = (const float*)d_in[7];
    float* out = (float*)d_out;

    const int E       = in_sizes[1] / 2;
    const int n_nodes = in_sizes[0] / 128;
    const int ntiles  = (E + TILE_E - 1) / TILE_E;
    const int smem_bytes = SMEM_W * 4;   // 231680 B

    static bool attr_set = false;
    if (!attr_set) {
        cudaFuncSetAttribute(lp_tc, cudaFuncAttributeMaxDynamicSharedMemorySize, smem_bytes);
        attr_set = true;
    }

    repack_w2<<<16, 512>>>(W2);

    int grid = 148;
    if (grid > ntiles) grid = ntiles;
    lp_tc<<<grid, NTHREADS, smem_bytes>>>(z, ei, W1, b1, b2, W3, b3, out, E, n_nodes, ntiles);
}